// round 15
// baseline (speedup 1.0000x reference)
#include <cuda_runtime.h>
#include <cuda_bf16.h>
#include <math.h>

typedef unsigned long long ull;

#define BBATCH 4
#define TSEQ   1024
#define CDIM   2048
#define HHEADS 32
#define NHEAD  64
#define MROWS  4096      // B*T
#define KVD    512
#define GN_EPS 0.00064f

// ---------------- packed f32x2 helpers ----------------
__device__ __forceinline__ ull pk2(float lo, float hi) {
    ull r; asm("mov.b64 %0,{%1,%2};" : "=l"(r) : "f"(lo), "f"(hi)); return r;
}
__device__ __forceinline__ void upk2(ull v, float& lo, float& hi) {
    asm("mov.b64 {%0,%1},%2;" : "=f"(lo), "=f"(hi) : "l"(v));
}
__device__ __forceinline__ ull fma2(ull a, ull b, ull c) {
    ull d; asm("fma.rn.f32x2 %0,%1,%2,%3;" : "=l"(d) : "l"(a), "l"(b), "l"(c)); return d;
}
__device__ __forceinline__ ull mul2(ull a, ull b) {
    ull d; asm("mul.rn.f32x2 %0,%1,%2;" : "=l"(d) : "l"(a), "l"(b)); return d;
}

// ---------------- scratch: __device__ globals (no allocation allowed) ----------------
__device__ float g_r [MROWS*CDIM];
__device__ float g_kf[MROWS*CDIM];
__device__ float g_vf[MROWS*CDIM];
__device__ float g_w [MROWS*CDIM];
__device__ float g_aa[MROWS*CDIM];
__device__ float g_bb[MROWS*CDIM];
__device__ float g_y [MROWS*CDIM];
__device__ float g_uw[MROWS*CDIM];
__device__ float g_ua[MROWS*CDIM];
__device__ float g_uv[MROWS*CDIM];
__device__ float g_k0[MROWS*KVD];
__device__ float g_v0[MROWS*KVD];
__device__ float g_tw[MROWS*64];
__device__ float g_ta[MROWS*64];
__device__ float g_tv[MROWS*32];
__device__ float g_w2T[CDIM*64];
__device__ float g_a2T[CDIM*64];
__device__ float g_v2T[CDIM*32];
__device__ float2 g_gn[BBATCH*HHEADS];

// bf16 hi/lo split buffers (preconverted once per launch)
__device__ __nv_bfloat16 g_xhi [MROWS*CDIM];
__device__ __nv_bfloat16 g_xlo [MROWS*CDIM];
__device__ __nv_bfloat16 g_xxhi[MROWS*CDIM];
__device__ __nv_bfloat16 g_xxlo[MROWS*CDIM];
__device__ __nv_bfloat16 g_Rhi [CDIM*CDIM];
__device__ __nv_bfloat16 g_Rlo [CDIM*CDIM];
__device__ __nv_bfloat16 g_Ohi [CDIM*CDIM];
__device__ __nv_bfloat16 g_Olo [CDIM*CDIM];
__device__ __nv_bfloat16 g_Khi [KVD*CDIM];
__device__ __nv_bfloat16 g_Klo [KVD*CDIM];
__device__ __nv_bfloat16 g_Vhi [KVD*CDIM];
__device__ __nv_bfloat16 g_Vlo [KVD*CDIM];

// =====================================================================
// fp32 -> bf16 hi/lo split (8 elems/thread)
// =====================================================================
__global__ void __launch_bounds__(256) cvt_split_kernel(
    const float* __restrict__ in, __nv_bfloat16* __restrict__ hi,
    __nv_bfloat16* __restrict__ lo, int n)
{
    int idx = (blockIdx.x * 256 + threadIdx.x) * 8;
    if (idx >= n) return;
    float4 f0 = *(const float4*)&in[idx];
    float4 f1 = *(const float4*)&in[idx + 4];
    float f[8] = {f0.x, f0.y, f0.z, f0.w, f1.x, f1.y, f1.z, f1.w};
    unsigned hh[4], ll[4];
    #pragma unroll
    for (int p = 0; p < 4; p++) {
        __nv_bfloat162 h = __floats2bfloat162_rn(f[2*p], f[2*p+1]);
        float r0 = f[2*p]   - __bfloat162float(h.x);
        float r1 = f[2*p+1] - __bfloat162float(h.y);
        __nv_bfloat162 l = __floats2bfloat162_rn(r0, r1);
        hh[p] = *reinterpret_cast<unsigned*>(&h);
        ll[p] = *reinterpret_cast<unsigned*>(&l);
    }
    *(uint4*)&hi[idx] = make_uint4(hh[0], hh[1], hh[2], hh[3]);
    *(uint4*)&lo[idx] = make_uint4(ll[0], ll[1], ll[2], ll[3]);
}

// =====================================================================
// HMMA bf16 GEMM, preconverted hi/lo inputs, cp.async pipeline
// =====================================================================
__device__ __forceinline__ unsigned smem_u32(const void* p) {
    unsigned a;
    asm("{ .reg .u64 t; cvta.to.shared.u64 t, %1; cvt.u32.u64 %0, t; }"
        : "=r"(a) : "l"(p));
    return a;
}
__device__ __forceinline__ void ldm4(unsigned* r, unsigned addr) {
    asm volatile("ldmatrix.sync.aligned.m8n8.x4.shared.b16 {%0,%1,%2,%3}, [%4];"
        : "=r"(r[0]), "=r"(r[1]), "=r"(r[2]), "=r"(r[3]) : "r"(addr));
}
__device__ __forceinline__ void mma16816(float* c, const unsigned* a, unsigned b0, unsigned b1) {
    asm volatile("mma.sync.aligned.m16n8k16.row.col.f32.bf16.bf16.f32 "
        "{%0,%1,%2,%3},{%4,%5,%6,%7},{%8,%9},{%0,%1,%2,%3};"
        : "+f"(c[0]), "+f"(c[1]), "+f"(c[2]), "+f"(c[3])
        : "r"(a[0]), "r"(a[1]), "r"(a[2]), "r"(a[3]), "r"(b0), "r"(b1));
}
__device__ __forceinline__ void cpa16(unsigned dst, const void* src) {
    asm volatile("cp.async.cg.shared.global [%0], [%1], 16;"
                 :: "r"(dst), "l"(src) : "memory");
}
__device__ __forceinline__ void cpa_commit() {
    asm volatile("cp.async.commit_group;" ::: "memory");
}
__device__ __forceinline__ void cpa_wait1() {
    asm volatile("cp.async.wait_group 1;" ::: "memory");
}
__device__ __forceinline__ void cpa_wait0() {
    asm volatile("cp.async.wait_group 0;" ::: "memory");
}

// smem layout: row stride 80B (40 bf16) -> conflict-free ldmatrix
#define HM_RSTRIDE 80
#define HM_AHI     0
#define HM_ALO     10240
#define HM_BHI     20480
#define HM_BLO     30720
#define HM_STAGE   40960
#define HM_SMEM    81920

// C[M,N] = A[M,K] @ B[N,K]^T (+bias); grid=(N/128, M/128), 256 threads; K%32==0
__global__ void __launch_bounds__(256, 2) hmma_gemm_kernel(
    const __nv_bfloat16* __restrict__ Ahi, const __nv_bfloat16* __restrict__ Alo,
    const __nv_bfloat16* __restrict__ Bhi, const __nv_bfloat16* __restrict__ Blo,
    const float* __restrict__ bias, float* __restrict__ Cout,
    int K, int N)
{
    extern __shared__ __align__(128) char sm[];
    unsigned sbase = smem_u32(sm);
    int tid = threadIdx.x, lane = tid & 31, wid = tid >> 5;
    int wm = wid >> 2, wn = wid & 3;              // 2 x 4 warp grid
    int bn = blockIdx.x * 128, bm = blockIdx.y * 128;

    // global loader: 2 threads per row, each owns 2x16B chunks (16 bf16)
    int lrow = tid >> 1, lhalf = tid & 1;
    size_t abase = (size_t)(bm + lrow) * K + lhalf * 16;
    size_t bbase = (size_t)(bn + lrow) * K + lhalf * 16;
    unsigned wr = (unsigned)(lrow * HM_RSTRIDE + lhalf * 32);

    // ldmatrix per-lane offsets
    int sub = lane >> 3, r8 = lane & 7;
    int rt16 = (sub & 1) * 8 + r8;
    int kt16 = (sub >> 1) * 8;
    unsigned a_off = (unsigned)((wm * 64 + rt16) * HM_RSTRIDE + kt16 * 2);
    unsigned b_off = (unsigned)((wn * 32 + rt16) * HM_RSTRIDE + kt16 * 2);

    float acc[4][4][4];
    #pragma unroll
    for (int i = 0; i < 4; i++)
        #pragma unroll
        for (int j = 0; j < 4; j++)
            #pragma unroll
            for (int q = 0; q < 4; q++) acc[i][j][q] = 0.f;

    int nch = K >> 5;

    // issue chunk c into slot s
    auto issue = [&](int c, int s) {
        unsigned so = sbase + (unsigned)s * HM_STAGE + wr;
        size_t ao = abase + (size_t)c * 32;
        size_t bo = bbase + (size_t)c * 32;
        cpa16(so + HM_AHI,      Ahi + ao);
        cpa16(so + HM_AHI + 16, Ahi + ao + 8);
        cpa16(so + HM_ALO,      Alo + ao);
        cpa16(so + HM_ALO + 16, Alo + ao + 8);
        cpa16(so + HM_BHI,      Bhi + bo);
        cpa16(so + HM_BHI + 16, Bhi + bo + 8);
        cpa16(so + HM_BLO,      Blo + bo);
        cpa16(so + HM_BLO + 16, Blo + bo + 8);
    };

    issue(0, 0); cpa_commit();
    issue(1, 1); cpa_commit();

    for (int c = 0; c < nch; c++) {
        if (c < nch - 1) cpa_wait1(); else cpa_wait0();
        __syncthreads();
        unsigned st = sbase + (unsigned)(c & 1) * HM_STAGE;
        #pragma unroll
        for (int k0 = 0; k0 < 32; k0 += 16) {
            unsigned ah[4][4], bh[2][4], xb[2][4];
            #pragma unroll
            for (int fm = 0; fm < 4; fm++) {
                unsigned ro = (unsigned)(fm * 16 * HM_RSTRIDE + k0 * 2);
                ldm4(ah[fm], st + HM_AHI + a_off + ro);
            }
            #pragma unroll
            for (int p = 0; p < 2; p++) {
                unsigned ro = (unsigned)(p * 16 * HM_RSTRIDE + k0 * 2);
                ldm4(bh[p], st + HM_BHI + b_off + ro);
            }
            // pass 1: Ahi * Bhi
            #pragma unroll
            for (int fm = 0; fm < 4; fm++)
                #pragma unroll
                for (int fn = 0; fn < 4; fn++) {
                    int p = fn >> 1, o = fn & 1;
                    mma16816(acc[fm][fn], ah[fm], bh[p][o], bh[p][2 + o]);
                }
            // pass 2: Ahi * Blo
            #pragma unroll
            for (int p = 0; p < 2; p++) {
                unsigned ro = (unsigned)(p * 16 * HM_RSTRIDE + k0 * 2);
                ldm4(xb[p], st + HM_BLO + b_off + ro);
            }
            #pragma unroll
            for (int fm = 0; fm < 4; fm++)
                #pragma unroll
                for (int fn = 0; fn < 4; fn++) {
                    int p = fn >> 1, o = fn & 1;
                    mma16816(acc[fm][fn], ah[fm], xb[p][o], xb[p][2 + o]);
                }
            // pass 3: Alo * Bhi (overwrite ah with al)
            #pragma unroll
            for (int fm = 0; fm < 4; fm++) {
                unsigned ro = (unsigned)(fm * 16 * HM_RSTRIDE + k0 * 2);
                ldm4(ah[fm], st + HM_ALO + a_off + ro);
            }
            #pragma unroll
            for (int fm = 0; fm < 4; fm++)
                #pragma unroll
                for (int fn = 0; fn < 4; fn++) {
                    int p = fn >> 1, o = fn & 1;
                    mma16816(acc[fm][fn], ah[fm], bh[p][o], bh[p][2 + o]);
                }
        }
        __syncthreads();
        if (c + 2 < nch) { issue(c + 2, c & 1); cpa_commit(); }
    }

    // epilogue
    int g = lane >> 2, tq = lane & 3;
    #pragma unroll
    for (int fm = 0; fm < 4; fm++) {
        int row = bm + wm * 64 + fm * 16 + g;
        #pragma unroll
        for (int fn = 0; fn < 4; fn++) {
            int col = bn + wn * 32 + fn * 8 + tq * 2;
            float bx = 0.f, by = 0.f;
            if (bias) { float2 bv = *(const float2*)&bias[col]; bx = bv.x; by = bv.y; }
            float* cc = acc[fm][fn];
            *(float2*)&Cout[(size_t)row * N + col] =
                make_float2(cc[0] + bx, cc[1] + by);
            *(float2*)&Cout[(size_t)(row + 8) * N + col] =
                make_float2(cc[2] + bx, cc[3] + by);
        }
    }
}

// ---------------- transpose for stage-2 LoRA weights ----------------
__global__ void transpose_kernel(const float* __restrict__ in, float* __restrict__ out,
                                 int rows, int cols) {
    int idx = blockIdx.x * 256 + threadIdx.x;
    if (idx < rows * cols) {
        int r = idx / cols, c = idx - r * cols;
        out[(size_t)c * rows + r] = in[idx];
    }
}

// ---------------- stage-1 LoRA: tanh(x@w1), x@a1, x@v1  (K=2048, N<=64) ----------------
__global__ void __launch_bounds__(256) lora1_kernel(
    const float* __restrict__ x, const float* __restrict__ w1,
    const float* __restrict__ a1w, const float* __restrict__ v1w)
{
    __shared__ __align__(16) float As[32][64];
    __shared__ __align__(16) float Bs[32][64];
    const float* Bw; float* outp; int Nw; int act = 0;
    if (blockIdx.y == 0)      { Bw = w1;  outp = g_tw; Nw = 64; act = 1; }
    else if (blockIdx.y == 1) { Bw = a1w; outp = g_ta; Nw = 64; }
    else                      { Bw = v1w; outp = g_tv; Nw = 32; }
    int m0 = blockIdx.x * 64, tid = threadIdx.x;
    int p = tid >> 4, q = tid & 15;
    int lr = tid >> 3, lc = (tid & 7) * 4;
    float acc[4][4] = {};
    for (int k0 = 0; k0 < CDIM; k0 += 32) {
        float4 a0v = *(const float4*)&x[(size_t)(m0 + lr) * CDIM + k0 + lc];
        float4 a1v = *(const float4*)&x[(size_t)(m0 + lr + 32) * CDIM + k0 + lc];
        float4 b0 = make_float4(0.f,0.f,0.f,0.f), b1 = make_float4(0.f,0.f,0.f,0.f);
        if (lc < Nw)      b0 = *(const float4*)&Bw[(size_t)(k0 + lr) * Nw + lc];
        if (lc + 32 < Nw) b1 = *(const float4*)&Bw[(size_t)(k0 + lr) * Nw + lc + 32];
        __syncthreads();
        As[lc+0][lr] = a0v.x; As[lc+1][lr] = a0v.y; As[lc+2][lr] = a0v.z; As[lc+3][lr] = a0v.w;
        As[lc+0][lr+32] = a1v.x; As[lc+1][lr+32] = a1v.y; As[lc+2][lr+32] = a1v.z; As[lc+3][lr+32] = a1v.w;
        *(float4*)&Bs[lr][lc]      = b0;
        *(float4*)&Bs[lr][lc + 32] = b1;
        __syncthreads();
        #pragma unroll
        for (int kk = 0; kk < 32; kk++) {
            float4 av = *(const float4*)&As[kk][p * 4];
            float4 bv = *(const float4*)&Bs[kk][q * 4];
            float af[4] = {av.x, av.y, av.z, av.w};
            float bf[4] = {bv.x, bv.y, bv.z, bv.w};
            #pragma unroll
            for (int ii = 0; ii < 4; ii++)
                #pragma unroll
                for (int jj = 0; jj < 4; jj++) acc[ii][jj] += af[ii] * bf[jj];
        }
    }
    #pragma unroll
    for (int ii = 0; ii < 4; ii++) {
        int row = m0 + p * 4 + ii;
        #pragma unroll
        for (int jj = 0; jj < 4; jj++) {
            int n = q * 4 + jj;
            if (n < Nw) {
                float v = acc[ii][jj];
                if (act) v = tanhf(v);
                outp[(size_t)row * Nw + n] = v;
            }
        }
    }
}

// ---------------- FFMA2 GEMM for all three LoRA stage-2 products (grid.z selects) ----------------
__global__ void __launch_bounds__(256) lora2_kernel()
{
    __shared__ __align__(16) float As[16][132];
    __shared__ __align__(16) float Bs[16][132];
    const float* A; const float* Bw; float* Cout; int K;
    if (blockIdx.z == 0)      { A = g_tw; Bw = g_w2T; Cout = g_uw; K = 64; }
    else if (blockIdx.z == 1) { A = g_ta; Bw = g_a2T; Cout = g_ua; K = 64; }
    else                      { A = g_tv; Bw = g_v2T; Cout = g_uv; K = 32; }
    const int N = CDIM;
    int bn = blockIdx.x * 128, bm = blockIdx.y * 128;
    int tid = threadIdx.x;
    int p = tid >> 4, q = tid & 15;
    int lr = tid >> 2, lc = (tid & 3) * 4;
    const float* Ap = A  + (size_t)(bm + lr) * K + lc;
    const float* Bp = Bw + (size_t)(bn + lr) * K + lc;
    ull acc[8][4];
    #pragma unroll
    for (int i2 = 0; i2 < 8; i2++)
        #pragma unroll
        for (int j2 = 0; j2 < 4; j2++) acc[i2][j2] = 0ULL;

    for (int k0 = 0; k0 < K; k0 += 16) {
        float4 a0 = *(const float4*)(Ap + k0);
        float4 a1 = *(const float4*)(Ap + (size_t)64 * K + k0);
        float4 b0 = *(const float4*)(Bp + k0);
        float4 b1 = *(const float4*)(Bp + (size_t)64 * K + k0);
        __syncthreads();
        As[lc+0][lr] = a0.x; As[lc+1][lr] = a0.y; As[lc+2][lr] = a0.z; As[lc+3][lr] = a0.w;
        As[lc+0][lr+64] = a1.x; As[lc+1][lr+64] = a1.y; As[lc+2][lr+64] = a1.z; As[lc+3][lr+64] = a1.w;
        Bs[lc+0][lr] = b0.x; Bs[lc+1][lr] = b0.y; Bs[lc+2][lr] = b0.z; Bs[lc+3][lr] = b0.w;
        Bs[lc+0][lr+64] = b1.x; Bs[lc+1][lr+64] = b1.y; Bs[lc+2][lr+64] = b1.z; Bs[lc+3][lr+64] = b1.w;
        __syncthreads();
        #pragma unroll
        for (int kk = 0; kk < 16; kk++) {
            float4 av0 = *(const float4*)&As[kk][p * 4];
            float4 av1 = *(const float4*)&As[kk][64 + p * 4];
            ulonglong2 bq0 = *(const ulonglong2*)&Bs[kk][q * 4];
            ulonglong2 bq1 = *(const ulonglong2*)&Bs[kk][64 + q * 4];
            float af[8] = {av0.x, av0.y, av0.z, av0.w, av1.x, av1.y, av1.z, av1.w};
            #pragma unroll
            for (int i2 = 0; i2 < 8; i2++) {
                ull ad = pk2(af[i2], af[i2]);
                acc[i2][0] = fma2(ad, bq0.x, acc[i2][0]);
                acc[i2][1] = fma2(ad, bq0.y, acc[i2][1]);
                acc[i2][2] = fma2(ad, bq1.x, acc[i2][2]);
                acc[i2][3] = fma2(ad, bq1.y, acc[i2][3]);
            }
        }
    }
    #pragma unroll
    for (int i2 = 0; i2 < 8; i2++) {
        int row = bm + p * 4 + ((i2 < 4) ? i2 : 60 + i2);
        float c[8];
        upk2(acc[i2][0], c[0], c[1]); upk2(acc[i2][1], c[2], c[3]);
        upk2(acc[i2][2], c[4], c[5]); upk2(acc[i2][3], c[6], c[7]);
        *(float4*)&Cout[(size_t)row * N + bn + q * 4] =
            make_float4(c[0], c[1], c[2], c[3]);
        *(float4*)&Cout[(size_t)row * N + bn + 64 + q * 4] =
            make_float4(c[4], c[5], c[6], c[7]);
    }
}

// ---------------- elementwise: kv-repeat, l2norm, gates, decay, v-blend ----------------
__global__ void __launch_bounds__(256) ew_kernel(
    const float* __restrict__ vfirst, const float* __restrict__ w0,
    const float* __restrict__ a0, const float* __restrict__ v0p,
    const float* __restrict__ kkw, const float* __restrict__ kaw)
{
    int m = blockIdx.x, tid = threadIdx.x;
    size_t base = (size_t)m * CDIM;
    int c0 = tid * 8;
    int ck0 = ((c0 >> 8) << 6) + (c0 & 63);   // kv-head replication map
    float kr[8], kkc[8];
    float ss = 0.f;
    #pragma unroll
    for (int j = 0; j < 8; j++) {
        kr[j] = g_k0[(size_t)m * KVD + ck0 + j];
        float t = kr[j] * kkw[c0 + j];
        kkc[j] = t; ss += t * t;
    }
    ss += __shfl_xor_sync(0xffffffffu, ss, 1);
    ss += __shfl_xor_sync(0xffffffffu, ss, 2);
    ss += __shfl_xor_sync(0xffffffffu, ss, 4);
    float inv = 1.f / fmaxf(sqrtf(ss), 1e-12f);
    #pragma unroll
    for (int j = 0; j < 8; j++) {
        int c = c0 + j;
        float av  = 1.f / (1.f + expf(-(a0[c] + g_ua[base + c])));
        float kkn = kkc[j] * inv;
        g_aa[base + c] = -kkn;
        g_bb[base + c] = kkn * av;
        g_kf[base + c] = kr[j] * (1.f + (av - 1.f) * kaw[c]);
        float vr = g_v0[(size_t)m * KVD + ck0 + j];
        float sg = 1.f / (1.f + expf(-(v0p[c] + g_uv[base + c])));
        g_vf[base + c] = vr + (vfirst[base + c] - vr) * sg;
        float z  = w0[c] + g_uw[base + c];
        float yy = -z;
        float sp = (yy > 20.f) ? yy : log1pf(expf(yy));
        g_w[base + c] = expf(-expf(-sp - 0.6f));
    }
}

// ---------------- RWKV-7 scan: 1 CTA/(b,h), 128 threads, double-buffered, fused gn stats ----------------
__device__ __forceinline__ const float* scan_src(int a) {
    switch (a) {
        case 0:  return g_r;  case 1: return g_w;  case 2: return g_kf;
        case 3:  return g_vf; case 4: return g_aa; default: return g_bb;
    }
}

__global__ void __launch_bounds__(128) scan_kernel(const float* __restrict__ state0)
{
    __shared__ __align__(16) float buf[2 * 384];   // 2 slots x 6 arrays x 64
    __shared__ float red[128];
    int blk = blockIdx.x, b = blk >> 5, h = blk & 31;
    int t = threadIdx.x, i = t >> 1, half = t & 1, cb = half * 32;
    ull S[16];
    const float* st = state0 + ((size_t)(b * HHEADS + h) * NHEAD + i) * NHEAD + cb;
    #pragma unroll
    for (int j = 0; j < 16; j++) S[j] = pk2(st[2 * j], st[2 * j + 1]);

    size_t hb = (size_t)(b * TSEQ) * CDIM + h * NHEAD;

    // each thread prefetches 3 of the 384 staged elements
    int f0 = t * 3;
    const float* s0 = scan_src( f0      >> 6); int o0 =  f0      & 63;
    const float* s1 = scan_src((f0 + 1) >> 6); int o1 = (f0 + 1) & 63;
    const float* s2 = scan_src((f0 + 2) >> 6); int o2 = (f0 + 2) & 63;

    // slot 0 <- t=0; regs <- t=1
    buf[f0] = s0[hb + o0]; buf[f0 + 1] = s1[hb + o1]; buf[f0 + 2] = s2[hb + o2];
    float p0 = 0.f, p1 = 0.f, p2 = 0.f;
    {
        size_t tb = hb + CDIM;
        p0 = s0[tb + o0]; p1 = s1[tb + o1]; p2 = s2[tb + o2];
    }
    __syncthreads();

    float sy = 0.f, sy2 = 0.f;
    for (int tt = 0; tt < TSEQ; tt++) {
        const float* base = buf + (tt & 1) * 384;
        const ull* R2 = (const ull*)(base + cb);
        const ull* W2 = (const ull*)(base + 64 + cb);
        const ull* K2 = (const ull*)(base + 128 + cb);
        const ull* A2 = (const ull*)(base + 256 + cb);
        const ull* B2 = (const ull*)(base + 320 + cb);
        float vi = base[192 + i];

        ull s0a = 0, s1a = 0, s2a = 0, s3a = 0;
        #pragma unroll
        for (int j = 0; j < 4; j++) {
            s0a = fma2(S[4*j    ], A2[4*j    ], s0a);
            s1a = fma2(S[4*j + 1], A2[4*j + 1], s1a);
            s2a = fma2(S[4*j + 2], A2[4*j + 2], s2a);
            s3a = fma2(S[4*j + 3], A2[4*j + 3], s3a);
        }
        float l0, h0, l1, h1;
        upk2(fma2(pk2(1.f,1.f), s0a, s1a), l0, h0);
        upk2(fma2(pk2(1.f,1.f), s2a, s3a), l1, h1);
        float sa = l0 + h0 + l1 + h1;
        sa += __shfl_xor_sync(0xffffffffu, sa, 1);

        ull sad = pk2(sa, sa), vid = pk2(vi, vi);
        ull y0 = 0, y1 = 0, y2 = 0, y3 = 0;
        #pragma unroll
        for (int j = 0; j < 4; j++) {
            S[4*j    ] = fma2(S[4*j    ], W2[4*j    ], fma2(sad, B2[4*j    ], mul2(vid, K2[4*j    ])));
            S[4*j + 1] = fma2(S[4*j + 1], W2[4*j + 1], fma2(sad, B2[4*j + 1], mul2(vid, K2[4*j + 1])));
            S[4*j + 2] = fma2(S[4*j + 2], W2[4*j + 2], fma2(sad, B2[4*j + 2], mul2(vid, K2[4*j + 2])));
            S[4*j + 3] = fma2(S[4*j + 3], W2[4*j + 3], fma2(sad, B2[4*j + 3], mul2(vid, K2[4*j + 3])));
            y0 = fma2(S[4*j    ], R2[4*j    ], y0);
            y1 = fma2(S[4*j + 1], R2[4*j + 1], y1);
            y2 = fma2(S[4*j + 2], R2[4*j + 2], y2);
            y3 = fma2(S[4*j + 3], R2[4*j + 3], y3);
        }
        upk2(fma2(pk2(1.f,1.f), y0, y1), l0, h0);
        upk2(fma2(pk2(1.f,1.f), y2, y3), l1, h1);
        float yv = l0 + h0 + l1 + h1;
        yv += __shfl_xor_sync(0xffffffffu, yv, 1);
        if (!half) {
            g_y[hb + (size_t)tt * CDIM + i] = yv;
            sy += yv; sy2 += yv * yv;
        }

        // stage t+1 into the other slot; prefetch t+2
        if (tt + 1 < TSEQ) {
            float* nb = buf + ((tt + 1) & 1) * 384;
            nb[f0] = p0; nb[f0 + 1] = p1; nb[f0 + 2] = p2;
            if (tt + 2 < TSEQ) {
                size_t tb = hb + (size_t)(tt + 2) * CDIM;
                p0 = s0[tb + o0]; p1 = s1[tb + o1]; p2 = s2[tb + o2];
            }
        }
        __syncthreads();
    }

    // fused group-norm stats: reduce 64 per-row (sy, sy2) pairs
    if (!half) { red[i] = sy; red[64 + i] = sy2; }
    __syncthreads();
    if (t == 0) {
        float S1 = 0.f, S2 = 0.f;
        for (int j = 0; j < 64; j++) { S1 += red[j]; S2 += red[64 + j]; }
        float mean = S1 * (1.f / 65536.f);
        float var  = S2 * (1.f / 65536.f) - mean * mean;
        g_gn[blk] = make_float2(mean, rsqrtf(var + GN_EPS));
    }
}

// ---------------- groupnorm apply + bonus -> bf16 hi/lo directly ----------------
__global__ void __launch_bounds__(256) fuse_kernel(
    const float* __restrict__ rkw, const float* __restrict__ lnw,
    const float* __restrict__ lnb)
{
    int m = blockIdx.x, tid = threadIdx.x;
    int c0 = tid * 8, h = c0 >> 6, b = m >> 10;
    float2 gn = g_gn[b * HHEADS + h];
    size_t base = (size_t)m * CDIM;
    float rr[8], kk[8];
    float dot = 0.f;
    #pragma unroll
    for (int j = 0; j < 8; j++) {
        rr[j] = g_r [base + c0 + j];
        kk[j] = g_kf[base + c0 + j];
        dot += rr[j] * kk[j] * rkw[c0 + j];
    }
    dot += __shfl_xor_sync(0xffffffffu, dot, 1);
    dot += __shfl_xor_sync(0xffffffffu, dot, 2);
    dot += __shfl_xor_sync(0xffffffffu, dot, 4);
    float f[8];
    #pragma unroll
    for (int j = 0; j < 8; j++) {
        int c = c0 + j;
        float yn = (g_y[base + c] - gn.x) * gn.y;
        f[j] = yn * lnw[c] + lnb[c] + dot * g_vf[base + c];
    }
    unsigned hh[4], ll[4];
    #pragma unroll
    for (int p = 0; p < 4; p++) {
        __nv_bfloat162 hv = __floats2bfloat162_rn(f[2*p], f[2*p+1]);
        float r0 = f[2*p]   - __bfloat162float(hv.x);
        float r1 = f[2*p+1] - __bfloat162float(hv.y);
        __nv_bfloat162 lv = __floats2bfloat162_rn(r0, r1);
        hh[p] = *reinterpret_cast<unsigned*>(&hv);
        ll[p] = *reinterpret_cast<unsigned*>(&lv);
    }
    *(uint4*)&g_xxhi[base + c0] = make_uint4(hh[0], hh[1], hh[2], hh[3]);
    *(uint4*)&g_xxlo[base + c0] = make_uint4(ll[0], ll[1], ll[2], ll[3]);
}

// ---------------- launch ----------------
extern "C" void kernel_launch(void* const* d_in, const int* in_sizes, int n_in,
                              void* d_out, int out_size)
{
    const float* x      = (const float*)d_in[0];
    const float* vfirst = (const float*)d_in[1];
    const float* state  = (const float*)d_in[2];
    const float* Rw = (const float*)d_in[3];  const float* Rb = (const float*)d_in[4];
    const float* Kw = (const float*)d_in[5];  const float* Kb = (const float*)d_in[6];
    const float* Vw = (const float*)d_in[7];  const float* Vb = (const float*)d_in[8];
    const float* Ow = (const float*)d_in[9];  const float* Ob = (const float*)d_in[10];
    const float* w0 = (const float*)d_in[11]; const float* w1 = (const float*)d_in[12];
    const float* w2 = (const float*)d_in[13];
    const float* a0 = (const float*)d_in[14]; const float* a1 = (const float*)d_in[15];
    const float* a2 = (const float*)d_in[16];
    const float* v0 = (const float*)d_in[17]; const float* v1 = (const float*)d_in[18];
    const float* v2 = (const float*)d_in[19];
    const float* kkw = (const float*)d_in[20]; const float* kaw = (const float*)d_in[21];
    const float* rkw = (const float*)d_in[22];
    const float* lnw = (const float*)d_in[23]; const float* lnb = (const float*)d_in[24];
    float* out = (float*)d_out;

    void *p_r, *p_k0, *p_v0, *p_w2T, *p_a2T, *p_v2T;
    void *p_xhi, *p_xlo, *p_xxhi, *p_xxlo;
    void *p_Rhi, *p_Rlo, *p_Ohi, *p_Olo, *p_Khi, *p_Klo, *p_Vhi, *p_Vlo;
    cudaGetSymbolAddress(&p_r,  g_r);  cudaGetSymbolAddress(&p_k0, g_k0);
    cudaGetSymbolAddress(&p_v0, g_v0);
    cudaGetSymbolAddress(&p_w2T, g_w2T);
    cudaGetSymbolAddress(&p_a2T, g_a2T); cudaGetSymbolAddress(&p_v2T, g_v2T);
    cudaGetSymbolAddress(&p_xhi,  g_xhi);  cudaGetSymbolAddress(&p_xlo,  g_xlo);
    cudaGetSymbolAddress(&p_xxhi, g_xxhi); cudaGetSymbolAddress(&p_xxlo, g_xxlo);
    cudaGetSymbolAddress(&p_Rhi,  g_Rhi);  cudaGetSymbolAddress(&p_Rlo,  g_Rlo);
    cudaGetSymbolAddress(&p_Ohi,  g_Ohi);  cudaGetSymbolAddress(&p_Olo,  g_Olo);
    cudaGetSymbolAddress(&p_Khi,  g_Khi);  cudaGetSymbolAddress(&p_Klo,  g_Klo);
    cudaGetSymbolAddress(&p_Vhi,  g_Vhi);  cudaGetSymbolAddress(&p_Vlo,  g_Vlo);

    cudaFuncSetAttribute(hmma_gemm_kernel, cudaFuncAttributeMaxDynamicSharedMemorySize, HM_SMEM);

    // hi/lo splits
    cvt_split_kernel<<<(MROWS*CDIM)/2048, 256>>>(x,  (__nv_bfloat16*)p_xhi, (__nv_bfloat16*)p_xlo, MROWS*CDIM);
    cvt_split_kernel<<<(CDIM*CDIM)/2048,  256>>>(Rw, (__nv_bfloat16*)p_Rhi, (__nv_bfloat16*)p_Rlo, CDIM*CDIM);
    cvt_split_kernel<<<(KVD*CDIM)/2048,   256>>>(Kw, (__nv_bfloat16*)p_Khi, (__nv_bfloat16*)p_Klo, KVD*CDIM);
    cvt_split_kernel<<<(KVD*CDIM)/2048,   256>>>(Vw, (__nv_bfloat16*)p_Vhi, (__nv_bfloat16*)p_Vlo, KVD*CDIM);
    cvt_split_kernel<<<(CDIM*CDIM)/2048,  256>>>(Ow, (__nv_bfloat16*)p_Ohi, (__nv_bfloat16*)p_Olo, CDIM*CDIM);

    // big projections (HMMA bf16 3-pass split, cp.async pipeline)
    hmma_gemm_kernel<<<dim3(16, 32), 256, HM_SMEM>>>(
        (const __nv_bfloat16*)p_xhi, (const __nv_bfloat16*)p_xlo,
        (const __nv_bfloat16*)p_Rhi, (const __nv_bfloat16*)p_Rlo, Rb, (float*)p_r, CDIM, CDIM);
    hmma_gemm_kernel<<<dim3(4, 32), 256, HM_SMEM>>>(
        (const __nv_bfloat16*)p_xhi, (const __nv_bfloat16*)p_xlo,
        (const __nv_bfloat16*)p_Khi, (const __nv_bfloat16*)p_Klo, Kb, (float*)p_k0, CDIM, KVD);
    hmma_gemm_kernel<<<dim3(4, 32), 256, HM_SMEM>>>(
        (const __nv_bfloat16*)p_xhi, (const __nv_bfloat16*)p_xlo,
        (const __nv_bfloat16*)p_Vhi, (const __nv_bfloat16*)p_Vlo, Vb, (float*)p_v0, CDIM, KVD);

    // stage-2 LoRA weight transposes (tiny)
    transpose_kernel<<<512, 256>>>(w2, (float*)p_w2T, 64, CDIM);
    transpose_kernel<<<512, 256>>>(a2, (float*)p_a2T, 64, CDIM);
    transpose_kernel<<<256, 256>>>(v2, (float*)p_v2T, 32, CDIM);

    // LoRA stage 1 + merged stage 2
    lora1_kernel<<<dim3(64, 3), 256>>>(x, w1, a1, v1);
    lora2_kernel<<<dim3(16, 32, 3), 256>>>();

    // elementwise prep
    ew_kernel<<<MROWS, 256>>>(vfirst, w0, a0, v0, kkw, kaw);

    // recurrent scan (double-buffered, fused gn stats)
    scan_kernel<<<BBATCH * HHEADS, 128>>>(state);

    // groupnorm apply + bonus -> bf16 hi/lo
    fuse_kernel<<<MROWS, 256>>>(rkw, lnw, lnb);

    // output projection (HMMA)
    hmma_gemm_kernel<<<dim3(16, 32), 256, HM_SMEM>>>(
        (const __nv_bfloat16*)p_xxhi, (const __nv_bfloat16*)p_xxlo,
        (const __nv_bfloat16*)p_Ohi, (const __nv_bfloat16*)p_Olo, Ob, out, CDIM, CDIM);
}

// round 16
// speedup vs baseline: 1.0801x; 1.0801x over previous
#include <cuda_runtime.h>
#include <cuda_bf16.h>
#include <math.h>

typedef unsigned long long ull;

#define BBATCH 4
#define TSEQ   1024
#define CDIM   2048
#define HHEADS 32
#define NHEAD  64
#define MROWS  4096      // B*T
#define KVD    512
#define GN_EPS 0.00064f

// ---------------- packed f32x2 helpers ----------------
__device__ __forceinline__ ull pk2(float lo, float hi) {
    ull r; asm("mov.b64 %0,{%1,%2};" : "=l"(r) : "f"(lo), "f"(hi)); return r;
}
__device__ __forceinline__ void upk2(ull v, float& lo, float& hi) {
    asm("mov.b64 {%0,%1},%2;" : "=f"(lo), "=f"(hi) : "l"(v));
}
__device__ __forceinline__ ull fma2(ull a, ull b, ull c) {
    ull d; asm("fma.rn.f32x2 %0,%1,%2,%3;" : "=l"(d) : "l"(a), "l"(b), "l"(c)); return d;
}
__device__ __forceinline__ ull mul2(ull a, ull b) {
    ull d; asm("mul.rn.f32x2 %0,%1,%2;" : "=l"(d) : "l"(a), "l"(b)); return d;
}

// ---------------- scratch: __device__ globals (no allocation allowed) ----------------
__device__ float g_r [MROWS*CDIM];
__device__ float g_kf[MROWS*CDIM];
__device__ float g_vf[MROWS*CDIM];
__device__ float g_w [MROWS*CDIM];
__device__ float g_aa[MROWS*CDIM];
__device__ float g_bb[MROWS*CDIM];
__device__ float g_y [MROWS*CDIM];
__device__ float g_uw[MROWS*CDIM];
__device__ float g_ua[MROWS*CDIM];
__device__ float g_uv[MROWS*CDIM];
__device__ float g_k0[MROWS*KVD];
__device__ float g_v0[MROWS*KVD];
__device__ float g_tw[MROWS*64];
__device__ float g_ta[MROWS*64];
__device__ float g_tv[MROWS*32];
__device__ float g_w2T[CDIM*64];
__device__ float g_a2T[CDIM*64];
__device__ float g_v2T[CDIM*32];
__device__ float2 g_gn[BBATCH*HHEADS];

// bf16 hi/lo split buffers (preconverted once per launch)
__device__ __nv_bfloat16 g_xhi [MROWS*CDIM];
__device__ __nv_bfloat16 g_xlo [MROWS*CDIM];
__device__ __nv_bfloat16 g_xxhi[MROWS*CDIM];
__device__ __nv_bfloat16 g_xxlo[MROWS*CDIM];
__device__ __nv_bfloat16 g_Rhi [CDIM*CDIM];
__device__ __nv_bfloat16 g_Rlo [CDIM*CDIM];
__device__ __nv_bfloat16 g_Ohi [CDIM*CDIM];
__device__ __nv_bfloat16 g_Olo [CDIM*CDIM];
__device__ __nv_bfloat16 g_Khi [KVD*CDIM];
__device__ __nv_bfloat16 g_Klo [KVD*CDIM];
__device__ __nv_bfloat16 g_Vhi [KVD*CDIM];
__device__ __nv_bfloat16 g_Vlo [KVD*CDIM];

// =====================================================================
// fp32 -> bf16 hi/lo split (8 elems/thread)
// =====================================================================
__global__ void __launch_bounds__(256) cvt_split_kernel(
    const float* __restrict__ in, __nv_bfloat16* __restrict__ hi,
    __nv_bfloat16* __restrict__ lo, int n)
{
    int idx = (blockIdx.x * 256 + threadIdx.x) * 8;
    if (idx >= n) return;
    float4 f0 = *(const float4*)&in[idx];
    float4 f1 = *(const float4*)&in[idx + 4];
    float f[8] = {f0.x, f0.y, f0.z, f0.w, f1.x, f1.y, f1.z, f1.w};
    unsigned hh[4], ll[4];
    #pragma unroll
    for (int p = 0; p < 4; p++) {
        __nv_bfloat162 h = __floats2bfloat162_rn(f[2*p], f[2*p+1]);
        float r0 = f[2*p]   - __bfloat162float(h.x);
        float r1 = f[2*p+1] - __bfloat162float(h.y);
        __nv_bfloat162 l = __floats2bfloat162_rn(r0, r1);
        hh[p] = *reinterpret_cast<unsigned*>(&h);
        ll[p] = *reinterpret_cast<unsigned*>(&l);
    }
    *(uint4*)&hi[idx] = make_uint4(hh[0], hh[1], hh[2], hh[3]);
    *(uint4*)&lo[idx] = make_uint4(ll[0], ll[1], ll[2], ll[3]);
}

// =====================================================================
// HMMA bf16 GEMM, preconverted hi/lo inputs, cp.async pipeline
// =====================================================================
__device__ __forceinline__ unsigned smem_u32(const void* p) {
    unsigned a;
    asm("{ .reg .u64 t; cvta.to.shared.u64 t, %1; cvt.u32.u64 %0, t; }"
        : "=r"(a) : "l"(p));
    return a;
}
__device__ __forceinline__ void ldm4(unsigned* r, unsigned addr) {
    asm volatile("ldmatrix.sync.aligned.m8n8.x4.shared.b16 {%0,%1,%2,%3}, [%4];"
        : "=r"(r[0]), "=r"(r[1]), "=r"(r[2]), "=r"(r[3]) : "r"(addr));
}
__device__ __forceinline__ void mma16816(float* c, const unsigned* a, unsigned b0, unsigned b1) {
    asm volatile("mma.sync.aligned.m16n8k16.row.col.f32.bf16.bf16.f32 "
        "{%0,%1,%2,%3},{%4,%5,%6,%7},{%8,%9},{%0,%1,%2,%3};"
        : "+f"(c[0]), "+f"(c[1]), "+f"(c[2]), "+f"(c[3])
        : "r"(a[0]), "r"(a[1]), "r"(a[2]), "r"(a[3]), "r"(b0), "r"(b1));
}
__device__ __forceinline__ void cpa16(unsigned dst, const void* src) {
    asm volatile("cp.async.cg.shared.global [%0], [%1], 16;"
                 :: "r"(dst), "l"(src) : "memory");
}
__device__ __forceinline__ void cpa_commit() {
    asm volatile("cp.async.commit_group;" ::: "memory");
}
__device__ __forceinline__ void cpa_wait1() {
    asm volatile("cp.async.wait_group 1;" ::: "memory");
}
__device__ __forceinline__ void cpa_wait0() {
    asm volatile("cp.async.wait_group 0;" ::: "memory");
}

// smem layout: row stride 80B (40 bf16) -> conflict-free ldmatrix
#define HM_RSTRIDE 80
#define HM_AHI     0
#define HM_ALO     10240
#define HM_BHI     20480
#define HM_BLO     30720
#define HM_STAGE   40960
#define HM_SMEM    81920

// shared GEMM body: C[128,128 tile at (bm,bn)] = A[M,K] @ B[N,K]^T (+bias)
__device__ __forceinline__ void hmma_gemm_body(
    const __nv_bfloat16* __restrict__ Ahi, const __nv_bfloat16* __restrict__ Alo,
    const __nv_bfloat16* __restrict__ Bhi, const __nv_bfloat16* __restrict__ Blo,
    const float* __restrict__ bias, float* __restrict__ Cout,
    int K, int N, int bm, int bn, char* sm)
{
    unsigned sbase = smem_u32(sm);
    int tid = threadIdx.x, lane = tid & 31, wid = tid >> 5;
    int wm = wid >> 2, wn = wid & 3;              // 2 x 4 warp grid

    // global loader: 2 threads per row, each owns 2x16B chunks (16 bf16)
    int lrow = tid >> 1, lhalf = tid & 1;
    size_t abase = (size_t)(bm + lrow) * K + lhalf * 16;
    size_t bbase = (size_t)(bn + lrow) * K + lhalf * 16;
    unsigned wr = (unsigned)(lrow * HM_RSTRIDE + lhalf * 32);

    // ldmatrix per-lane offsets
    int sub = lane >> 3, r8 = lane & 7;
    int rt16 = (sub & 1) * 8 + r8;
    int kt16 = (sub >> 1) * 8;
    unsigned a_off = (unsigned)((wm * 64 + rt16) * HM_RSTRIDE + kt16 * 2);
    unsigned b_off = (unsigned)((wn * 32 + rt16) * HM_RSTRIDE + kt16 * 2);

    float acc[4][4][4];
    #pragma unroll
    for (int i = 0; i < 4; i++)
        #pragma unroll
        for (int j = 0; j < 4; j++)
            #pragma unroll
            for (int q = 0; q < 4; q++) acc[i][j][q] = 0.f;

    int nch = K >> 5;

    // issue chunk c into slot s
    auto issue = [&](int c, int s) {
        unsigned so = sbase + (unsigned)s * HM_STAGE + wr;
        size_t ao = abase + (size_t)c * 32;
        size_t bo = bbase + (size_t)c * 32;
        cpa16(so + HM_AHI,      Ahi + ao);
        cpa16(so + HM_AHI + 16, Ahi + ao + 8);
        cpa16(so + HM_ALO,      Alo + ao);
        cpa16(so + HM_ALO + 16, Alo + ao + 8);
        cpa16(so + HM_BHI,      Bhi + bo);
        cpa16(so + HM_BHI + 16, Bhi + bo + 8);
        cpa16(so + HM_BLO,      Blo + bo);
        cpa16(so + HM_BLO + 16, Blo + bo + 8);
    };

    issue(0, 0); cpa_commit();
    issue(1, 1); cpa_commit();

    for (int c = 0; c < nch; c++) {
        if (c < nch - 1) cpa_wait1(); else cpa_wait0();
        __syncthreads();
        unsigned st = sbase + (unsigned)(c & 1) * HM_STAGE;
        #pragma unroll
        for (int k0 = 0; k0 < 32; k0 += 16) {
            unsigned ah[4][4], bh[2][4], xb[2][4];
            #pragma unroll
            for (int fm = 0; fm < 4; fm++) {
                unsigned ro = (unsigned)(fm * 16 * HM_RSTRIDE + k0 * 2);
                ldm4(ah[fm], st + HM_AHI + a_off + ro);
            }
            #pragma unroll
            for (int p = 0; p < 2; p++) {
                unsigned ro = (unsigned)(p * 16 * HM_RSTRIDE + k0 * 2);
                ldm4(bh[p], st + HM_BHI + b_off + ro);
            }
            // pass 1: Ahi * Bhi
            #pragma unroll
            for (int fm = 0; fm < 4; fm++)
                #pragma unroll
                for (int fn = 0; fn < 4; fn++) {
                    int p = fn >> 1, o = fn & 1;
                    mma16816(acc[fm][fn], ah[fm], bh[p][o], bh[p][2 + o]);
                }
            // pass 2: Ahi * Blo
            #pragma unroll
            for (int p = 0; p < 2; p++) {
                unsigned ro = (unsigned)(p * 16 * HM_RSTRIDE + k0 * 2);
                ldm4(xb[p], st + HM_BLO + b_off + ro);
            }
            #pragma unroll
            for (int fm = 0; fm < 4; fm++)
                #pragma unroll
                for (int fn = 0; fn < 4; fn++) {
                    int p = fn >> 1, o = fn & 1;
                    mma16816(acc[fm][fn], ah[fm], xb[p][o], xb[p][2 + o]);
                }
            // pass 3: Alo * Bhi (overwrite ah with al)
            #pragma unroll
            for (int fm = 0; fm < 4; fm++) {
                unsigned ro = (unsigned)(fm * 16 * HM_RSTRIDE + k0 * 2);
                ldm4(ah[fm], st + HM_ALO + a_off + ro);
            }
            #pragma unroll
            for (int fm = 0; fm < 4; fm++)
                #pragma unroll
                for (int fn = 0; fn < 4; fn++) {
                    int p = fn >> 1, o = fn & 1;
                    mma16816(acc[fm][fn], ah[fm], bh[p][o], bh[p][2 + o]);
                }
        }
        __syncthreads();
        if (c + 2 < nch) { issue(c + 2, c & 1); cpa_commit(); }
    }

    // epilogue
    int g = lane >> 2, tq = lane & 3;
    #pragma unroll
    for (int fm = 0; fm < 4; fm++) {
        int row = bm + wm * 64 + fm * 16 + g;
        #pragma unroll
        for (int fn = 0; fn < 4; fn++) {
            int col = bn + wn * 32 + fn * 8 + tq * 2;
            float bx = 0.f, by = 0.f;
            if (bias) { float2 bv = *(const float2*)&bias[col]; bx = bv.x; by = bv.y; }
            float* cc = acc[fm][fn];
            *(float2*)&Cout[(size_t)row * N + col] =
                make_float2(cc[0] + bx, cc[1] + by);
            *(float2*)&Cout[(size_t)(row + 8) * N + col] =
                make_float2(cc[2] + bx, cc[3] + by);
        }
    }
}

// C[M,N] = A[M,K] @ B[N,K]^T (+bias); grid=(N/128, M/128), 256 threads; K%32==0
__global__ void __launch_bounds__(256, 2) hmma_gemm_kernel(
    const __nv_bfloat16* __restrict__ Ahi, const __nv_bfloat16* __restrict__ Alo,
    const __nv_bfloat16* __restrict__ Bhi, const __nv_bfloat16* __restrict__ Blo,
    const float* __restrict__ bias, float* __restrict__ Cout,
    int K, int N)
{
    extern __shared__ __align__(128) char sm[];
    hmma_gemm_body(Ahi, Alo, Bhi, Blo, bias, Cout, K, N,
                   blockIdx.y * 128, blockIdx.x * 128, sm);
}

// merged K+V projection: grid=(8, 32); bx<4 -> K tile, bx>=4 -> V tile
__global__ void __launch_bounds__(256, 2) hmma_gemm_kv_kernel(
    const __nv_bfloat16* __restrict__ Ahi, const __nv_bfloat16* __restrict__ Alo,
    const __nv_bfloat16* __restrict__ KBhi, const __nv_bfloat16* __restrict__ KBlo,
    const float* __restrict__ Kb, float* __restrict__ Kout,
    const __nv_bfloat16* __restrict__ VBhi, const __nv_bfloat16* __restrict__ VBlo,
    const float* __restrict__ Vb, float* __restrict__ Vout)
{
    extern __shared__ __align__(128) char sm[];
    int bx = blockIdx.x;
    if (bx < 4)
        hmma_gemm_body(Ahi, Alo, KBhi, KBlo, Kb, Kout, CDIM, KVD,
                       blockIdx.y * 128, bx * 128, sm);
    else
        hmma_gemm_body(Ahi, Alo, VBhi, VBlo, Vb, Vout, CDIM, KVD,
                       blockIdx.y * 128, (bx - 4) * 128, sm);
}

// ---------------- transpose for stage-2 LoRA weights ----------------
__global__ void transpose_kernel(const float* __restrict__ in, float* __restrict__ out,
                                 int rows, int cols) {
    int idx = blockIdx.x * 256 + threadIdx.x;
    if (idx < rows * cols) {
        int r = idx / cols, c = idx - r * cols;
        out[(size_t)c * rows + r] = in[idx];
    }
}

// ---------------- stage-1 LoRA: tanh(x@w1), x@a1, x@v1  (K=2048, N<=64) ----------------
__global__ void __launch_bounds__(256) lora1_kernel(
    const float* __restrict__ x, const float* __restrict__ w1,
    const float* __restrict__ a1w, const float* __restrict__ v1w)
{
    __shared__ __align__(16) float As[32][64];
    __shared__ __align__(16) float Bs[32][64];
    const float* Bw; float* outp; int Nw; int act = 0;
    if (blockIdx.y == 0)      { Bw = w1;  outp = g_tw; Nw = 64; act = 1; }
    else if (blockIdx.y == 1) { Bw = a1w; outp = g_ta; Nw = 64; }
    else                      { Bw = v1w; outp = g_tv; Nw = 32; }
    int m0 = blockIdx.x * 64, tid = threadIdx.x;
    int p = tid >> 4, q = tid & 15;
    int lr = tid >> 3, lc = (tid & 7) * 4;
    float acc[4][4] = {};
    for (int k0 = 0; k0 < CDIM; k0 += 32) {
        float4 a0v = *(const float4*)&x[(size_t)(m0 + lr) * CDIM + k0 + lc];
        float4 a1v = *(const float4*)&x[(size_t)(m0 + lr + 32) * CDIM + k0 + lc];
        float4 b0 = make_float4(0.f,0.f,0.f,0.f), b1 = make_float4(0.f,0.f,0.f,0.f);
        if (lc < Nw)      b0 = *(const float4*)&Bw[(size_t)(k0 + lr) * Nw + lc];
        if (lc + 32 < Nw) b1 = *(const float4*)&Bw[(size_t)(k0 + lr) * Nw + lc + 32];
        __syncthreads();
        As[lc+0][lr] = a0v.x; As[lc+1][lr] = a0v.y; As[lc+2][lr] = a0v.z; As[lc+3][lr] = a0v.w;
        As[lc+0][lr+32] = a1v.x; As[lc+1][lr+32] = a1v.y; As[lc+2][lr+32] = a1v.z; As[lc+3][lr+32] = a1v.w;
        *(float4*)&Bs[lr][lc]      = b0;
        *(float4*)&Bs[lr][lc + 32] = b1;
        __syncthreads();
        #pragma unroll
        for (int kk = 0; kk < 32; kk++) {
            float4 av = *(const float4*)&As[kk][p * 4];
            float4 bv = *(const float4*)&Bs[kk][q * 4];
            float af[4] = {av.x, av.y, av.z, av.w};
            float bf[4] = {bv.x, bv.y, bv.z, bv.w};
            #pragma unroll
            for (int ii = 0; ii < 4; ii++)
                #pragma unroll
                for (int jj = 0; jj < 4; jj++) acc[ii][jj] += af[ii] * bf[jj];
        }
    }
    #pragma unroll
    for (int ii = 0; ii < 4; ii++) {
        int row = m0 + p * 4 + ii;
        #pragma unroll
        for (int jj = 0; jj < 4; jj++) {
            int n = q * 4 + jj;
            if (n < Nw) {
                float v = acc[ii][jj];
                if (act) v = tanhf(v);
                outp[(size_t)row * Nw + n] = v;
            }
        }
    }
}

// ---------------- FFMA2 GEMM (kept for K=64/32 LoRA stage-2) ----------------
__global__ void __launch_bounds__(256) gemm_nt_kernel(
    const float* __restrict__ A, const float* __restrict__ Bw,
    const float* __restrict__ bias, float* __restrict__ Cout,
    int K, int N)
{
    __shared__ __align__(16) float As[16][132];
    __shared__ __align__(16) float Bs[16][132];
    int bn = blockIdx.x * 128, bm = blockIdx.y * 128;
    int tid = threadIdx.x;
    int p = tid >> 4, q = tid & 15;
    int lr = tid >> 2, lc = (tid & 3) * 4;
    const float* Ap = A  + (size_t)(bm + lr) * K + lc;
    const float* Bp = Bw + (size_t)(bn + lr) * K + lc;
    ull acc[8][4];
    #pragma unroll
    for (int i2 = 0; i2 < 8; i2++)
        #pragma unroll
        for (int j2 = 0; j2 < 4; j2++) acc[i2][j2] = 0ULL;

    for (int k0 = 0; k0 < K; k0 += 16) {
        float4 a0 = *(const float4*)(Ap + k0);
        float4 a1 = *(const float4*)(Ap + (size_t)64 * K + k0);
        float4 b0 = *(const float4*)(Bp + k0);
        float4 b1 = *(const float4*)(Bp + (size_t)64 * K + k0);
        __syncthreads();
        As[lc+0][lr] = a0.x; As[lc+1][lr] = a0.y; As[lc+2][lr] = a0.z; As[lc+3][lr] = a0.w;
        As[lc+0][lr+64] = a1.x; As[lc+1][lr+64] = a1.y; As[lc+2][lr+64] = a1.z; As[lc+3][lr+64] = a1.w;
        Bs[lc+0][lr] = b0.x; Bs[lc+1][lr] = b0.y; Bs[lc+2][lr] = b0.z; Bs[lc+3][lr] = b0.w;
        Bs[lc+0][lr+64] = b1.x; Bs[lc+1][lr+64] = b1.y; Bs[lc+2][lr+64] = b1.z; Bs[lc+3][lr+64] = b1.w;
        __syncthreads();
        #pragma unroll
        for (int kk = 0; kk < 16; kk++) {
            float4 av0 = *(const float4*)&As[kk][p * 4];
            float4 av1 = *(const float4*)&As[kk][64 + p * 4];
            ulonglong2 bq0 = *(const ulonglong2*)&Bs[kk][q * 4];
            ulonglong2 bq1 = *(const ulonglong2*)&Bs[kk][64 + q * 4];
            float af[8] = {av0.x, av0.y, av0.z, av0.w, av1.x, av1.y, av1.z, av1.w};
            #pragma unroll
            for (int i2 = 0; i2 < 8; i2++) {
                ull ad = pk2(af[i2], af[i2]);
                acc[i2][0] = fma2(ad, bq0.x, acc[i2][0]);
                acc[i2][1] = fma2(ad, bq0.y, acc[i2][1]);
                acc[i2][2] = fma2(ad, bq1.x, acc[i2][2]);
                acc[i2][3] = fma2(ad, bq1.y, acc[i2][3]);
            }
        }
    }
    float bl[8] = {0.f,0.f,0.f,0.f,0.f,0.f,0.f,0.f};
    if (bias) {
        float4 x0 = *(const float4*)&bias[bn + q * 4];
        float4 x1 = *(const float4*)&bias[bn + 64 + q * 4];
        bl[0]=x0.x; bl[1]=x0.y; bl[2]=x0.z; bl[3]=x0.w;
        bl[4]=x1.x; bl[5]=x1.y; bl[6]=x1.z; bl[7]=x1.w;
    }
    #pragma unroll
    for (int i2 = 0; i2 < 8; i2++) {
        int row = bm + p * 4 + ((i2 < 4) ? i2 : 60 + i2);
        float c[8];
        upk2(acc[i2][0], c[0], c[1]); upk2(acc[i2][1], c[2], c[3]);
        upk2(acc[i2][2], c[4], c[5]); upk2(acc[i2][3], c[6], c[7]);
        float4 o0 = make_float4(c[0]+bl[0], c[1]+bl[1], c[2]+bl[2], c[3]+bl[3]);
        float4 o1 = make_float4(c[4]+bl[4], c[5]+bl[5], c[6]+bl[6], c[7]+bl[7]);
        *(float4*)&Cout[(size_t)row * N + bn + q * 4]      = o0;
        *(float4*)&Cout[(size_t)row * N + bn + 64 + q * 4] = o1;
    }
}

// ---------------- elementwise: kv-repeat, l2norm, gates, decay, v-blend ----------------
__global__ void __launch_bounds__(256) ew_kernel(
    const float* __restrict__ vfirst, const float* __restrict__ w0,
    const float* __restrict__ a0, const float* __restrict__ v0p,
    const float* __restrict__ kkw, const float* __restrict__ kaw)
{
    int m = blockIdx.x, tid = threadIdx.x;
    size_t base = (size_t)m * CDIM;
    int c0 = tid * 8;
    int ck0 = ((c0 >> 8) << 6) + (c0 & 63);   // kv-head replication map
    float kr[8], kkc[8];
    float ss = 0.f;
    #pragma unroll
    for (int j = 0; j < 8; j++) {
        kr[j] = g_k0[(size_t)m * KVD + ck0 + j];
        float t = kr[j] * kkw[c0 + j];
        kkc[j] = t; ss += t * t;
    }
    ss += __shfl_xor_sync(0xffffffffu, ss, 1);
    ss += __shfl_xor_sync(0xffffffffu, ss, 2);
    ss += __shfl_xor_sync(0xffffffffu, ss, 4);
    float inv = 1.f / fmaxf(sqrtf(ss), 1e-12f);
    #pragma unroll
    for (int j = 0; j < 8; j++) {
        int c = c0 + j;
        float av  = 1.f / (1.f + expf(-(a0[c] + g_ua[base + c])));
        float kkn = kkc[j] * inv;
        g_aa[base + c] = -kkn;
        g_bb[base + c] = kkn * av;
        g_kf[base + c] = kr[j] * (1.f + (av - 1.f) * kaw[c]);
        float vr = g_v0[(size_t)m * KVD + ck0 + j];
        float sg = 1.f / (1.f + expf(-(v0p[c] + g_uv[base + c])));
        g_vf[base + c] = vr + (vfirst[base + c] - vr) * sg;
        float z  = w0[c] + g_uw[base + c];
        float yy = -z;
        float sp = (yy > 20.f) ? yy : log1pf(expf(yy));
        g_w[base + c] = expf(-expf(-sp - 0.6f));
    }
}

// ---------------- RWKV-7 scan: 1 CTA/(b,h), 128 threads (2 per row), packed state ----------------
__device__ __forceinline__ const float* scan_src(int a) {
    switch (a) {
        case 0:  return g_r;  case 1: return g_w;  case 2: return g_kf;
        case 3:  return g_vf; case 4: return g_aa; default: return g_bb;
    }
}

__global__ void __launch_bounds__(128) scan_kernel(const float* __restrict__ state0)
{
    __shared__ __align__(16) float buf[384];   // 6 arrays x 64 floats
    int blk = blockIdx.x, b = blk >> 5, h = blk & 31;
    int t = threadIdx.x, i = t >> 1, half = t & 1, cb = half * 32;
    ull S[16];
    const float* st = state0 + ((size_t)(b * HHEADS + h) * NHEAD + i) * NHEAD + cb;
    #pragma unroll
    for (int j = 0; j < 16; j++) S[j] = pk2(st[2 * j], st[2 * j + 1]);

    size_t hb = (size_t)(b * TSEQ) * CDIM + h * NHEAD;

    // each thread prefetches 3 of the 384 staged elements
    int f0 = t * 3;
    const float* s0 = scan_src( f0      >> 6); int o0 =  f0      & 63;
    const float* s1 = scan_src((f0 + 1) >> 6); int o1 = (f0 + 1) & 63;
    const float* s2 = scan_src((f0 + 2) >> 6); int o2 = (f0 + 2) & 63;
    float p0 = s0[hb + o0], p1 = s1[hb + o1], p2 = s2[hb + o2];

    for (int tt = 0; tt < TSEQ; tt++) {
        buf[f0] = p0; buf[f0 + 1] = p1; buf[f0 + 2] = p2;
        __syncthreads();
        if (tt + 1 < TSEQ) {
            size_t tb = hb + (size_t)(tt + 1) * CDIM;
            p0 = s0[tb + o0]; p1 = s1[tb + o1]; p2 = s2[tb + o2];
        }
        const ull* R2 = (const ull*)(buf + cb);
        const ull* W2 = (const ull*)(buf + 64 + cb);
        const ull* K2 = (const ull*)(buf + 128 + cb);
        const ull* A2 = (const ull*)(buf + 256 + cb);
        const ull* B2 = (const ull*)(buf + 320 + cb);
        float vi = buf[192 + i];

        ull s0a = 0, s1a = 0, s2a = 0, s3a = 0;
        #pragma unroll
        for (int j = 0; j < 4; j++) {
            s0a = fma2(S[4*j    ], A2[4*j    ], s0a);
            s1a = fma2(S[4*j + 1], A2[4*j + 1], s1a);
            s2a = fma2(S[4*j + 2], A2[4*j + 2], s2a);
            s3a = fma2(S[4*j + 3], A2[4*j + 3], s3a);
        }
        float l0, h0, l1, h1;
        upk2(fma2(pk2(1.f,1.f), s0a, s1a), l0, h0);
        upk2(fma2(pk2(1.f,1.f), s2a, s3a), l1, h1);
        float sa = l0 + h0 + l1 + h1;
        sa += __shfl_xor_sync(0xffffffffu, sa, 1);

        ull sad = pk2(sa, sa), vid = pk2(vi, vi);
        ull y0 = 0, y1 = 0, y2 = 0, y3 = 0;
        #pragma unroll
        for (int j = 0; j < 4; j++) {
            S[4*j    ] = fma2(S[4*j    ], W2[4*j    ], fma2(sad, B2[4*j    ], mul2(vid, K2[4*j    ])));
            S[4*j + 1] = fma2(S[4*j + 1], W2[4*j + 1], fma2(sad, B2[4*j + 1], mul2(vid, K2[4*j + 1])));
            S[4*j + 2] = fma2(S[4*j + 2], W2[4*j + 2], fma2(sad, B2[4*j + 2], mul2(vid, K2[4*j + 2])));
            S[4*j + 3] = fma2(S[4*j + 3], W2[4*j + 3], fma2(sad, B2[4*j + 3], mul2(vid, K2[4*j + 3])));
            y0 = fma2(S[4*j    ], R2[4*j    ], y0);
            y1 = fma2(S[4*j + 1], R2[4*j + 1], y1);
            y2 = fma2(S[4*j + 2], R2[4*j + 2], y2);
            y3 = fma2(S[4*j + 3], R2[4*j + 3], y3);
        }
        upk2(fma2(pk2(1.f,1.f), y0, y1), l0, h0);
        upk2(fma2(pk2(1.f,1.f), y2, y3), l1, h1);
        float yv = l0 + h0 + l1 + h1;
        yv += __shfl_xor_sync(0xffffffffu, yv, 1);
        if (!half) g_y[hb + (size_t)tt * CDIM + i] = yv;
        __syncthreads();
    }
}

// ---------------- group-norm stats per (b,h) over (T,N) ----------------
__global__ void __launch_bounds__(256) gn_kernel()
{
    int blk = blockIdx.x, b = blk >> 5, h = blk & 31;
    size_t hb = (size_t)(b * TSEQ) * CDIM + h * NHEAD;
    int tid = threadIdx.x, n = tid & 63, tq = tid >> 6;
    float s = 0.f, s2 = 0.f;
    for (int t = tq; t < TSEQ; t += 4) {
        float v = g_y[hb + (size_t)t * CDIM + n];
        s += v; s2 += v * v;
    }
    #pragma unroll
    for (int o = 16; o; o >>= 1) {
        s  += __shfl_xor_sync(0xffffffffu, s,  o);
        s2 += __shfl_xor_sync(0xffffffffu, s2, o);
    }
    __shared__ float sh[16];
    if ((tid & 31) == 0) { sh[(tid >> 5) * 2] = s; sh[(tid >> 5) * 2 + 1] = s2; }
    __syncthreads();
    if (tid == 0) {
        float S = 0.f, S2 = 0.f;
        for (int w = 0; w < 8; w++) { S += sh[2 * w]; S2 += sh[2 * w + 1]; }
        float mean = S * (1.f / 65536.f);
        float var  = S2 * (1.f / 65536.f) - mean * mean;
        g_gn[blk] = make_float2(mean, rsqrtf(var + GN_EPS));
    }
}

// ---------------- groupnorm apply + bonus -> bf16 hi/lo directly ----------------
__global__ void __launch_bounds__(256) fuse_kernel(
    const float* __restrict__ rkw, const float* __restrict__ lnw,
    const float* __restrict__ lnb)
{
    int m = blockIdx.x, tid = threadIdx.x;
    int c0 = tid * 8, h = c0 >> 6, b = m >> 10;
    float2 gn = g_gn[b * HHEADS + h];
    size_t base = (size_t)m * CDIM;
    float rr[8], kk[8];
    float dot = 0.f;
    #pragma unroll
    for (int j = 0; j < 8; j++) {
        rr[j] = g_r [base + c0 + j];
        kk[j] = g_kf[base + c0 + j];
        dot += rr[j] * kk[j] * rkw[c0 + j];
    }
    dot += __shfl_xor_sync(0xffffffffu, dot, 1);
    dot += __shfl_xor_sync(0xffffffffu, dot, 2);
    dot += __shfl_xor_sync(0xffffffffu, dot, 4);
    float f[8];
    #pragma unroll
    for (int j = 0; j < 8; j++) {
        int c = c0 + j;
        float yn = (g_y[base + c] - gn.x) * gn.y;
        f[j] = yn * lnw[c] + lnb[c] + dot * g_vf[base + c];
    }
    unsigned hh[4], ll[4];
    #pragma unroll
    for (int p = 0; p < 4; p++) {
        __nv_bfloat162 hv = __floats2bfloat162_rn(f[2*p], f[2*p+1]);
        float r0 = f[2*p]   - __bfloat162float(hv.x);
        float r1 = f[2*p+1] - __bfloat162float(hv.y);
        __nv_bfloat162 lv = __floats2bfloat162_rn(r0, r1);
        hh[p] = *reinterpret_cast<unsigned*>(&hv);
        ll[p] = *reinterpret_cast<unsigned*>(&lv);
    }
    *(uint4*)&g_xxhi[base + c0] = make_uint4(hh[0], hh[1], hh[2], hh[3]);
    *(uint4*)&g_xxlo[base + c0] = make_uint4(ll[0], ll[1], ll[2], ll[3]);
}

// ---------------- launch ----------------
extern "C" void kernel_launch(void* const* d_in, const int* in_sizes, int n_in,
                              void* d_out, int out_size)
{
    const float* x      = (const float*)d_in[0];
    const float* vfirst = (const float*)d_in[1];
    const float* state  = (const float*)d_in[2];
    const float* Rw = (const float*)d_in[3];  const float* Rb = (const float*)d_in[4];
    const float* Kw = (const float*)d_in[5];  const float* Kb = (const float*)d_in[6];
    const float* Vw = (const float*)d_in[7];  const float* Vb = (const float*)d_in[8];
    const float* Ow = (const float*)d_in[9];  const float* Ob = (const float*)d_in[10];
    const float* w0 = (const float*)d_in[11]; const float* w1 = (const float*)d_in[12];
    const float* w2 = (const float*)d_in[13];
    const float* a0 = (const float*)d_in[14]; const float* a1 = (const float*)d_in[15];
    const float* a2 = (const float*)d_in[16];
    const float* v0 = (const float*)d_in[17]; const float* v1 = (const float*)d_in[18];
    const float* v2 = (const float*)d_in[19];
    const float* kkw = (const float*)d_in[20]; const float* kaw = (const float*)d_in[21];
    const float* rkw = (const float*)d_in[22];
    const float* lnw = (const float*)d_in[23]; const float* lnb = (const float*)d_in[24];
    float* out = (float*)d_out;

    void *p_r, *p_k0, *p_v0, *p_tw, *p_ta, *p_tv, *p_uw, *p_ua, *p_uv;
    void *p_w2T, *p_a2T, *p_v2T;
    void *p_xhi, *p_xlo, *p_xxhi, *p_xxlo;
    void *p_Rhi, *p_Rlo, *p_Ohi, *p_Olo, *p_Khi, *p_Klo, *p_Vhi, *p_Vlo;
    cudaGetSymbolAddress(&p_r,  g_r);  cudaGetSymbolAddress(&p_k0, g_k0);
    cudaGetSymbolAddress(&p_v0, g_v0); cudaGetSymbolAddress(&p_tw, g_tw);
    cudaGetSymbolAddress(&p_ta, g_ta); cudaGetSymbolAddress(&p_tv, g_tv);
    cudaGetSymbolAddress(&p_uw, g_uw); cudaGetSymbolAddress(&p_ua, g_ua);
    cudaGetSymbolAddress(&p_uv, g_uv); cudaGetSymbolAddress(&p_w2T, g_w2T);
    cudaGetSymbolAddress(&p_a2T, g_a2T); cudaGetSymbolAddress(&p_v2T, g_v2T);
    cudaGetSymbolAddress(&p_xhi,  g_xhi);  cudaGetSymbolAddress(&p_xlo,  g_xlo);
    cudaGetSymbolAddress(&p_xxhi, g_xxhi); cudaGetSymbolAddress(&p_xxlo, g_xxlo);
    cudaGetSymbolAddress(&p_Rhi,  g_Rhi);  cudaGetSymbolAddress(&p_Rlo,  g_Rlo);
    cudaGetSymbolAddress(&p_Ohi,  g_Ohi);  cudaGetSymbolAddress(&p_Olo,  g_Olo);
    cudaGetSymbolAddress(&p_Khi,  g_Khi);  cudaGetSymbolAddress(&p_Klo,  g_Klo);
    cudaGetSymbolAddress(&p_Vhi,  g_Vhi);  cudaGetSymbolAddress(&p_Vlo,  g_Vlo);

    cudaFuncSetAttribute(hmma_gemm_kernel,    cudaFuncAttributeMaxDynamicSharedMemorySize, HM_SMEM);
    cudaFuncSetAttribute(hmma_gemm_kv_kernel, cudaFuncAttributeMaxDynamicSharedMemorySize, HM_SMEM);

    // hi/lo splits
    cvt_split_kernel<<<(MROWS*CDIM)/2048, 256>>>(x,  (__nv_bfloat16*)p_xhi, (__nv_bfloat16*)p_xlo, MROWS*CDIM);
    cvt_split_kernel<<<(CDIM*CDIM)/2048,  256>>>(Rw, (__nv_bfloat16*)p_Rhi, (__nv_bfloat16*)p_Rlo, CDIM*CDIM);
    cvt_split_kernel<<<(KVD*CDIM)/2048,   256>>>(Kw, (__nv_bfloat16*)p_Khi, (__nv_bfloat16*)p_Klo, KVD*CDIM);
    cvt_split_kernel<<<(KVD*CDIM)/2048,   256>>>(Vw, (__nv_bfloat16*)p_Vhi, (__nv_bfloat16*)p_Vlo, KVD*CDIM);
    cvt_split_kernel<<<(CDIM*CDIM)/2048,  256>>>(Ow, (__nv_bfloat16*)p_Ohi, (__nv_bfloat16*)p_Olo, CDIM*CDIM);

    // big projections: R, then merged K+V (one wave instead of two half-empty ones)
    hmma_gemm_kernel<<<dim3(16, 32), 256, HM_SMEM>>>(
        (const __nv_bfloat16*)p_xhi, (const __nv_bfloat16*)p_xlo,
        (const __nv_bfloat16*)p_Rhi, (const __nv_bfloat16*)p_Rlo, Rb, (float*)p_r, CDIM, CDIM);
    hmma_gemm_kv_kernel<<<dim3(8, 32), 256, HM_SMEM>>>(
        (const __nv_bfloat16*)p_xhi, (const __nv_bfloat16*)p_xlo,
        (const __nv_bfloat16*)p_Khi, (const __nv_bfloat16*)p_Klo, Kb, (float*)p_k0,
        (const __nv_bfloat16*)p_Vhi, (const __nv_bfloat16*)p_Vlo, Vb, (float*)p_v0);

    // stage-2 LoRA weight transposes (tiny)
    transpose_kernel<<<512, 256>>>(w2, (float*)p_w2T, 64, CDIM);
    transpose_kernel<<<512, 256>>>(a2, (float*)p_a2T, 64, CDIM);
    transpose_kernel<<<256, 256>>>(v2, (float*)p_v2T, 32, CDIM);

    // LoRA stage 1 + stage 2
    lora1_kernel<<<dim3(64, 3), 256>>>(x, w1, a1, v1);
    gemm_nt_kernel<<<dim3(16, 32), 256>>>((const float*)p_tw, (const float*)p_w2T,
                                          nullptr, (float*)p_uw, 64, CDIM);
    gemm_nt_kernel<<<dim3(16, 32), 256>>>((const float*)p_ta, (const float*)p_a2T,
                                          nullptr, (float*)p_ua, 64, CDIM);
    gemm_nt_kernel<<<dim3(16, 32), 256>>>((const float*)p_tv, (const float*)p_v2T,
                                          nullptr, (float*)p_uv, 32, CDIM);

    // elementwise prep
    ew_kernel<<<MROWS, 256>>>(vfirst, w0, a0, v0, kkw, kaw);

    // recurrent scan (R14 form: 128 threads, single staging buffer)
    scan_kernel<<<BBATCH * HHEADS, 128>>>(state);

    // group norm + fused apply/bonus -> bf16 hi/lo
    gn_kernel<<<BBATCH * HHEADS, 256>>>();
    fuse_kernel<<<MROWS, 256>>>(rkw, lnw, lnb);

    // output projection (HMMA)
    hmma_gemm_kernel<<<dim3(16, 32), 256, HM_SMEM>>>(
        (const __nv_bfloat16*)p_xxhi, (const __nv_bfloat16*)p_xxlo,
        (const __nv_bfloat16*)p_Ohi, (const __nv_bfloat16*)p_Olo, Ob, out, CDIM, CDIM);
}